// round 5
// baseline (speedup 1.0000x reference)
#include <cuda_runtime.h>
#include <math.h>

// Problem constants  (reference: C_M, C_Z, C, H = 256, 128, 32, 8)
#define S_DIM 128
#define R_DIM 384
#define CM    256
#define CZ    128
#define H_DIM 8
#define C_DIM 32
#define HC    256          // H*C
#define MROWS (S_DIM*R_DIM)  // 49152
#define EPSLN 1e-5f

// ---------------- scratch (static device globals; no runtime alloc) ----------------
__device__ float g_mn[MROWS * CM];                       // LN(m), [m][cm]
__device__ float g_q [S_DIM*H_DIM*R_DIM*C_DIM];          // [s][h][r][c]  (pre-scaled 1/sqrt(C))
__device__ float g_k [S_DIM*H_DIM*R_DIM*C_DIM];
__device__ float g_v [S_DIM*H_DIM*R_DIM*C_DIM];
__device__ float g_gate[MROWS * HC];                     // sigmoid(mn@Wg+bg), [m][(h,c)]
__device__ float g_bias[H_DIM*R_DIM*R_DIM];              // [h][q][k]
__device__ float g_o[MROWS * HC];                        // gated attention out, [m][(h,c)]

// ---------------- 1. LayerNorm of m ----------------
__global__ void __launch_bounds__(256) ln_m_kernel(const float* __restrict__ m,
                                                   const float* __restrict__ gamma,
                                                   const float* __restrict__ beta) {
    int row = blockIdx.x;          // 0..49151
    int tid = threadIdx.x;         // 0..255
    float x = m[(size_t)row*CM + tid];
    float s = x, s2 = x*x;
    #pragma unroll
    for (int o = 16; o > 0; o >>= 1) {
        s  += __shfl_xor_sync(0xffffffffu, s,  o);
        s2 += __shfl_xor_sync(0xffffffffu, s2, o);
    }
    __shared__ float rs[8], rs2[8];
    int wid = tid >> 5, lane = tid & 31;
    if (lane == 0) { rs[wid] = s; rs2[wid] = s2; }
    __syncthreads();
    if (wid == 0) {
        float a = (lane < 8) ? rs[lane]  : 0.f;
        float b = (lane < 8) ? rs2[lane] : 0.f;
        #pragma unroll
        for (int o = 4; o > 0; o >>= 1) {
            a += __shfl_xor_sync(0xffffffffu, a, o);
            b += __shfl_xor_sync(0xffffffffu, b, o);
        }
        if (lane == 0) { rs[0] = a; rs2[0] = b; }
    }
    __syncthreads();
    float mu  = rs[0]  * (1.f/256.f);
    float var = rs2[0] * (1.f/256.f) - mu*mu;
    g_mn[(size_t)row*CM + tid] = (x - mu) * rsqrtf(var + EPSLN) * gamma[tid] + beta[tid];
}

// ---------------- 2. pair bias: b[h][q][k] = LN(z[q,k,:]) @ Wb[:,h], CZ=128 ----------------
__global__ void __launch_bounds__(256) pair_bias_kernel(const float* __restrict__ z,
                                                        const float* __restrict__ gz,
                                                        const float* __restrict__ bz,
                                                        const float* __restrict__ Wb) {
    int gw   = (blockIdx.x * blockDim.x + threadIdx.x) >> 5;   // one warp per (q,k)
    int lane = threadIdx.x & 31;
    if (gw >= R_DIM * R_DIM) return;
    int qr = gw / R_DIM, kr = gw % R_DIM;
    const float* zp = z + (size_t)gw * CZ;

    float x[4];
    float s = 0.f, s2 = 0.f;
    #pragma unroll
    for (int j = 0; j < 4; j++) {
        x[j] = zp[lane + 32*j];
        s  += x[j];
        s2 += x[j]*x[j];
    }
    #pragma unroll
    for (int o = 16; o > 0; o >>= 1) {
        s  += __shfl_xor_sync(0xffffffffu, s,  o);
        s2 += __shfl_xor_sync(0xffffffffu, s2, o);
    }
    float mu  = s  * (1.f/128.f);
    float var = s2 * (1.f/128.f) - mu*mu;
    float inv = rsqrtf(var + EPSLN);

    float zn[4];
    #pragma unroll
    for (int j = 0; j < 4; j++)
        zn[j] = (x[j] - mu) * inv * gz[lane + 32*j] + bz[lane + 32*j];

    #pragma unroll
    for (int h = 0; h < H_DIM; h++) {
        float p = 0.f;
        #pragma unroll
        for (int j = 0; j < 4; j++)
            p += zn[j] * Wb[(lane + 32*j) * H_DIM + h];
        #pragma unroll
        for (int o = 16; o > 0; o >>= 1) p += __shfl_xor_sync(0xffffffffu, p, o);
        if (lane == 0)
            g_bias[((size_t)h * R_DIM + qr) * R_DIM + kr] = p;
    }
}

// ---------------- 3. QKVG projections: 128x128x8 SGEMM, fused epilogues ----------------
__global__ void __launch_bounds__(256) proj_gemm_kernel(const float* __restrict__ Wq,
                                                        const float* __restrict__ Wk,
                                                        const float* __restrict__ Wv,
                                                        const float* __restrict__ Wg,
                                                        const float* __restrict__ bg) {
    const int proj = blockIdx.z;
    const float* B = (proj == 0) ? Wq : (proj == 1) ? Wk : (proj == 2) ? Wv : Wg;

    __shared__ float As[8][128];
    __shared__ float Bs[8][128];

    int tid = threadIdx.x;
    int tx = tid & 15, ty = tid >> 4;
    int m0 = blockIdx.y * 128, n0 = blockIdx.x * 128;

    float acc[8][8];
    #pragma unroll
    for (int i = 0; i < 8; i++)
        #pragma unroll
        for (int j = 0; j < 8; j++) acc[i][j] = 0.f;

    int arow = tid >> 1, ac4 = (tid & 1) * 4;
    int brow = tid >> 5, bc4 = (tid & 31) * 4;
    const float* Ap = g_mn + (size_t)(m0 + arow) * CM + ac4;
    const float* Bp = B    + (size_t)brow * HC + n0 + bc4;

    for (int k0 = 0; k0 < CM; k0 += 8) {
        float4 a = *(const float4*)(Ap + k0);
        float4 b = *(const float4*)(Bp + (size_t)k0 * HC);
        As[ac4+0][arow] = a.x; As[ac4+1][arow] = a.y;
        As[ac4+2][arow] = a.z; As[ac4+3][arow] = a.w;
        *(float4*)&Bs[brow][bc4] = b;
        __syncthreads();
        #pragma unroll
        for (int kk = 0; kk < 8; kk++) {
            float af[8], bf[8];
            #pragma unroll
            for (int i = 0; i < 8; i++) af[i] = As[kk][ty*8 + i];
            #pragma unroll
            for (int j = 0; j < 8; j++) bf[j] = Bs[kk][tx*8 + j];
            #pragma unroll
            for (int i = 0; i < 8; i++)
                #pragma unroll
                for (int j = 0; j < 8; j++) acc[i][j] += af[i] * bf[j];
        }
        __syncthreads();
    }

    #pragma unroll
    for (int i = 0; i < 8; i++) {
        int gm = m0 + ty*8 + i;
        int sI = gm / R_DIM, r = gm % R_DIM;
        #pragma unroll
        for (int j = 0; j < 8; j++) {
            int gn = n0 + tx*8 + j;
            float val = acc[i][j];
            if (proj == 3) {
                val = 1.f / (1.f + expf(-(val + bg[gn])));
                g_gate[(size_t)gm * HC + gn] = val;
            } else {
                int h = gn >> 5, c = gn & 31;
                size_t idx = ((size_t)(sI * H_DIM + h) * R_DIM + r) * C_DIM + c;
                if (proj == 0)      g_q[idx] = val * 0.17677669529663687f; // 1/sqrt(32)
                else if (proj == 1) g_k[idx] = val;
                else                g_v[idx] = val;
            }
        }
    }
}

// ---------------- 4. FUSED attention: logits + softmax + AV + gate ----------------
// Block: one (s,h) batch, one 64-row q-tile. Scores kept in smem, exact softmax,
// split-K P@V. Removes the 604MB logits tensor entirely.
#define QT 64
// float offsets into dynamic smem
#define OFF_SS 0                              // [64][385]
#define OFF_VS (OFF_SS + 64*385)              // [384][33]
#define OFF_QS (OFF_VS + 384*33)              // [64][33]
#define OFF_KS (OFF_QS + 64*33)               // [64][33]
#define OFF_OS (OFF_KS + 64*33)               // [4][64][33]
#define SMEM_FLOATS (OFF_OS + 4*64*33)        // 49984 floats = 199936 bytes
#define SS(r,k)   sm[OFF_SS + (r)*385 + (k)]
#define VS(k,c)   sm[OFF_VS + (k)*33 + (c)]
#define QS(r,c)   sm[OFF_QS + (r)*33 + (c)]
#define KS(r,c)   sm[OFF_KS + (r)*33 + (c)]
#define OS(p,q,c) sm[OFF_OS + (p)*(64*33) + (q)*33 + (c)]

__global__ void __launch_bounds__(256) attn_fused_kernel() {
    extern __shared__ float sm[];
    int bz = blockIdx.y;                 // (s,h) = s*8+h
    int sI = bz >> 3, h = bz & 7;
    int q0t = blockIdx.x * QT;
    int tid = threadIdx.x;

    const float* Qb = g_q + ((size_t)bz * R_DIM + q0t) * C_DIM;
    const float* Kb = g_k + (size_t)bz * R_DIM * C_DIM;
    const float* Vb = g_v + (size_t)bz * R_DIM * C_DIM;
    const float* bb = g_bias + ((size_t)h * R_DIM + q0t) * R_DIM;

    // ---- load Q tile (64x32) ----
    #pragma unroll
    for (int it = 0; it < 2; it++) {
        int i = tid + 256*it;            // 0..511
        int row = i >> 3, c4 = (i & 7) << 2;
        float4 v = *(const float4*)(Qb + (size_t)row * C_DIM + c4);
        QS(row, c4+0) = v.x; QS(row, c4+1) = v.y;
        QS(row, c4+2) = v.z; QS(row, c4+3) = v.w;
    }

    // ---- Phase A: scores = Q K^T + bias, chunked over k ----
    int ty = tid >> 5;        // warp id 0..7 -> q rows ty+8i
    int tx = tid & 31;        // k = kc + tx + 32j
    for (int kc = 0; kc < R_DIM; kc += 64) {
        // load K chunk (64x32) and V chunk into persistent VS
        #pragma unroll
        for (int it = 0; it < 2; it++) {
            int i = tid + 256*it;
            int row = i >> 3, c4 = (i & 7) << 2;
            float4 kv = *(const float4*)(Kb + (size_t)(kc+row) * C_DIM + c4);
            float4 vv = *(const float4*)(Vb + (size_t)(kc+row) * C_DIM + c4);
            KS(row, c4+0) = kv.x; KS(row, c4+1) = kv.y;
            KS(row, c4+2) = kv.z; KS(row, c4+3) = kv.w;
            VS(kc+row, c4+0) = vv.x; VS(kc+row, c4+1) = vv.y;
            VS(kc+row, c4+2) = vv.z; VS(kc+row, c4+3) = vv.w;
        }
        __syncthreads();

        float acc[8][2];
        #pragma unroll
        for (int i = 0; i < 8; i++)
            #pragma unroll
            for (int j = 0; j < 2; j++)
                acc[i][j] = bb[(size_t)(ty + 8*i) * R_DIM + kc + tx + 32*j];

        #pragma unroll
        for (int c = 0; c < 32; c++) {
            float qf[8], kf[2];
            #pragma unroll
            for (int i = 0; i < 8; i++) qf[i] = QS(ty + 8*i, c);   // warp-uniform broadcast
            #pragma unroll
            for (int j = 0; j < 2; j++) kf[j] = KS(tx + 32*j, c);  // conflict-free strided
            #pragma unroll
            for (int i = 0; i < 8; i++)
                #pragma unroll
                for (int j = 0; j < 2; j++) acc[i][j] += qf[i] * kf[j];
        }

        #pragma unroll
        for (int i = 0; i < 8; i++)
            #pragma unroll
            for (int j = 0; j < 2; j++)
                SS(ty + 8*i, kc + tx + 32*j) = acc[i][j];
        __syncthreads();
    }

    // ---- Phase B: exact softmax over the 384 k's, in smem ----
    {
        int wid = tid >> 5, lane = tid & 31;
        #pragma unroll
        for (int rr = 0; rr < 8; rr++) {
            int r = wid*8 + rr;
            float l[12];
            float mx = -1e30f;
            #pragma unroll
            for (int t = 0; t < 12; t++) {
                l[t] = SS(r, lane + 32*t);
                mx = fmaxf(mx, l[t]);
            }
            #pragma unroll
            for (int o = 16; o > 0; o >>= 1) mx = fmaxf(mx, __shfl_xor_sync(0xffffffffu, mx, o));
            float s = 0.f;
            #pragma unroll
            for (int t = 0; t < 12; t++) { l[t] = __expf(l[t] - mx); s += l[t]; }
            #pragma unroll
            for (int o = 16; o > 0; o >>= 1) s += __shfl_xor_sync(0xffffffffu, s, o);
            float inv = 1.f / s;
            #pragma unroll
            for (int t = 0; t < 12; t++) SS(r, lane + 32*t) = l[t] * inv;
        }
    }
    __syncthreads();

    // ---- Phase C: O = P @ V, split-K x4 ----
    {
        int part = tid >> 6;         // 0..3, k range [part*96, part*96+96)
        int t    = tid & 63;
        int qg   = t >> 3;           // rows qg + 8i
        int cg   = t & 7;            // cols cg + 8j
        float acc[8][4];
        #pragma unroll
        for (int i = 0; i < 8; i++)
            #pragma unroll
            for (int j = 0; j < 4; j++) acc[i][j] = 0.f;

        int k0 = part * 96;
        for (int k = k0; k < k0 + 96; k++) {
            float pf[8], vf[4];
            #pragma unroll
            for (int i = 0; i < 8; i++) pf[i] = SS(qg + 8*i, k);
            #pragma unroll
            for (int j = 0; j < 4; j++) vf[j] = VS(k, cg + 8*j);
            #pragma unroll
            for (int i = 0; i < 8; i++)
                #pragma unroll
                for (int j = 0; j < 4; j++) acc[i][j] += pf[i] * vf[j];
        }
        #pragma unroll
        for (int i = 0; i < 8; i++)
            #pragma unroll
            for (int j = 0; j < 4; j++)
                OS(part, qg + 8*i, cg + 8*j) = acc[i][j];
    }
    __syncthreads();

    // ---- reduce partitions, gate, write ----
    #pragma unroll
    for (int u = 0; u < 8; u++) {
        int e = tid + 256*u;         // 0..2047
        int q = e >> 5, c = e & 31;
        float val = OS(0,q,c) + OS(1,q,c) + OS(2,q,c) + OS(3,q,c);
        size_t mlin = (size_t)sI * R_DIM + q0t + q;
        size_t idx  = mlin * HC + h * C_DIM + c;
        g_o[idx] = val * g_gate[idx];
    }
}

// ---------------- 7. out = (g*o) @ Wo + bo : 128x128x8 SGEMM ----------------
__global__ void __launch_bounds__(256) out_gemm_kernel(const float* __restrict__ Wo,
                                                       const float* __restrict__ bo,
                                                       float* __restrict__ out) {
    __shared__ float As[8][128];
    __shared__ float Bs[8][128];

    int tid = threadIdx.x;
    int tx = tid & 15, ty = tid >> 4;
    int m0 = blockIdx.y * 128, n0 = blockIdx.x * 128;

    float acc[8][8];
    #pragma unroll
    for (int i = 0; i < 8; i++)
        #pragma unroll
        for (int j = 0; j < 8; j++) acc[i][j] = 0.f;

    int arow = tid >> 1, ac4 = (tid & 1) * 4;
    int brow = tid >> 5, bc4 = (tid & 31) * 4;
    const float* Ap = g_o + (size_t)(m0 + arow) * HC + ac4;
    const float* Bp = Wo  + (size_t)brow * CM + n0 + bc4;

    for (int k0 = 0; k0 < HC; k0 += 8) {
        float4 a = *(const float4*)(Ap + k0);
        float4 b = *(const float4*)(Bp + (size_t)k0 * CM);
        As[ac4+0][arow] = a.x; As[ac4+1][arow] = a.y;
        As[ac4+2][arow] = a.z; As[ac4+3][arow] = a.w;
        *(float4*)&Bs[brow][bc4] = b;
        __syncthreads();
        #pragma unroll
        for (int kk = 0; kk < 8; kk++) {
            float af[8], bf[8];
            #pragma unroll
            for (int i = 0; i < 8; i++) af[i] = As[kk][ty*8 + i];
            #pragma unroll
            for (int j = 0; j < 8; j++) bf[j] = Bs[kk][tx*8 + j];
            #pragma unroll
            for (int i = 0; i < 8; i++)
                #pragma unroll
                for (int j = 0; j < 8; j++) acc[i][j] += af[i] * bf[j];
        }
        __syncthreads();
    }

    #pragma unroll
    for (int i = 0; i < 8; i++) {
        int gm = m0 + ty*8 + i;
        #pragma unroll
        for (int j = 0; j < 8; j++) {
            int gn = n0 + tx*8 + j;
            out[(size_t)gm * CM + gn] = acc[i][j] + bo[gn];
        }
    }
}

// ---------------- launch ----------------
extern "C" void kernel_launch(void* const* d_in, const int* in_sizes, int n_in,
                              void* d_out, int out_size) {
    const float* m      = (const float*)d_in[0];
    const float* z      = (const float*)d_in[1];
    const float* ln_m_g = (const float*)d_in[2];
    const float* ln_m_b = (const float*)d_in[3];
    const float* ln_z_g = (const float*)d_in[4];
    const float* ln_z_b = (const float*)d_in[5];
    const float* Wq     = (const float*)d_in[6];
    const float* Wk     = (const float*)d_in[7];
    const float* Wv     = (const float*)d_in[8];
    const float* Wb     = (const float*)d_in[9];
    const float* Wg     = (const float*)d_in[10];
    const float* bg     = (const float*)d_in[11];
    const float* Wo     = (const float*)d_in[12];
    const float* bo     = (const float*)d_in[13];
    float* out = (float*)d_out;

    const int SMEM_BYTES = SMEM_FLOATS * 4;   // 199936
    static int smem_set = 0;
    if (!smem_set) {
        cudaFuncSetAttribute(attn_fused_kernel,
                             cudaFuncAttributeMaxDynamicSharedMemorySize, SMEM_BYTES);
        smem_set = 1;
    }

    // 1. LN(m)
    ln_m_kernel<<<MROWS, 256>>>(m, ln_m_g, ln_m_b);
    // 2. pair bias (warp per (q,k), CZ=128)
    pair_bias_kernel<<<(R_DIM*R_DIM + 7) / 8, 256>>>(z, ln_z_g, ln_z_b, Wb);
    // 3. Q/K/V/G projections
    proj_gemm_kernel<<<dim3(2, MROWS/128, 4), 256>>>(Wq, Wk, Wv, Wg, bg);
    // 4-6. fused attention (6 q-tiles x 1024 (s,h) batches)
    attn_fused_kernel<<<dim3(R_DIM/QT, S_DIM*H_DIM), 256, SMEM_BYTES>>>();
    // 7. output projection
    out_gemm_kernel<<<dim3(2, MROWS/128, 1), 256>>>(Wo, bo, out);
}